// round 3
// baseline (speedup 1.0000x reference)
#include <cuda_runtime.h>
#include <cstdint>

#define B_   64
#define T_   1152
#define C_   64
#define F_   8
#define KH_  32
#define PAD_ 15

typedef unsigned long long ull;

// ---------------- scratch (device globals; no allocation allowed) ----------
__device__ float g_M[B_ * 4 * C_];                      // folded spatial_w^T @ L_norm
__device__ float g_snn[(size_t)B_ * T_ * 32];           // snn_in (B,T,32)  ~9.4 MB
__device__ float g_flat[B_ * 3072];                     // chunk-mean features
__device__ int   g_spk;                                 // spike count (spk1+spk2)

// ---------------- f32x2 helpers (sm_100+) ----------------------------------
__device__ __forceinline__ ull pack_dup(float x) {
    unsigned int xi = __float_as_uint(x);
    ull r;
    asm("mov.b64 %0, {%1, %1};" : "=l"(r) : "r"(xi));
    return r;
}
__device__ __forceinline__ ull fma2(ull a, ull b, ull c) {
    ull d;
    asm("fma.rn.f32x2 %0, %1, %2, %3;" : "=l"(d) : "l"(a), "l"(b), "l"(c));
    return d;
}
__device__ __forceinline__ void unpack2(ull v, float& lo, float& hi) {
    unsigned int l, h;
    asm("mov.b64 {%0, %1}, %2;" : "=r"(l), "=r"(h) : "l"(v));
    lo = __uint_as_float(l);
    hi = __uint_as_float(h);
}

// ---------------- K0: fold spatial_w into L_norm, zero counters ------------
__global__ void k0_prep(const float* __restrict__ Ln, const float* __restrict__ spw) {
    int b   = blockIdx.x;
    int tid = threadIdx.x;          // 256 threads: (s,m)
    int s = tid >> 6, m = tid & 63;
    const float* L = Ln + b * 4096;
    float acc = 0.f;
#pragma unroll 8
    for (int c = 0; c < 64; ++c)
        acc += spw[c * 4 + s] * L[c * 64 + m];
    g_M[b * 256 + s * 64 + m] = acc;
    if (b == 0 && tid == 0) g_spk = 0;
}

// ---------------- K1: conv(32 taps) + LN + ReLU + M-projection -------------
// grid (T/8, B), block 128: tid = c (0..63) + 64*g (g=0,1); each thread does
// 4 consecutive timesteps via a rolling 4-row register window (f32x2-dup'd).
// Invariant: at the start of tap kh, slot (r & 3) holds relative row r for
// r in [kh, kh+3]; output tt at tap kh consumes row kh+tt. Rows run to
// kh_max + tt_max = 34, hence refills must continue while kh < 31.
__global__ void __launch_bounds__(128)
k1_conv(const float* __restrict__ X, const float* __restrict__ Kg,
        const float* __restrict__ lnS, const float* __restrict__ lnB) {
    __shared__ ull   sK2[1024];       // conv kernel as f32x2 pairs: [kh][i][op]
    __shared__ float sM[256];         // M[s][c] for this b
    __shared__ float sLN[16];         // scale[8], bias[8]
    __shared__ float sAnn[8 * 577];   // ann tile [t_loc][c*9 + o]

    int tid   = threadIdx.x;
    int b     = blockIdx.y;
    int t_blk = blockIdx.x * 8;

    const ull* Kg2 = (const ull*)Kg;
    for (int i = tid; i < 1024; i += 128) sK2[i] = Kg2[i];
    for (int i = tid; i < 256;  i += 128) sM[i]  = g_M[b * 256 + i];
    if (tid < 8) { sLN[tid] = lnS[tid]; sLN[8 + tid] = lnB[tid]; }
    __syncthreads();

    int c = tid & 63;
    int g = tid >> 6;
    int t_first = t_blk + g * 4;
    const float* Xb = X + ((size_t)b * T_ * C_ + c) * F_;

    ull rw[4][8];                     // rolling window of 4 input rows (dup'd)
    ull acc[4][4];                    // [tt][op]  (op packs channels 2op,2op+1)
#pragma unroll
    for (int tt = 0; tt < 4; ++tt)
#pragma unroll
        for (int op = 0; op < 4; ++op) acc[tt][op] = 0ull;

#pragma unroll
    for (int slot = 0; slot < 4; ++slot) {
        int t_in = t_first - PAD_ + slot;
        if ((unsigned)t_in < (unsigned)T_) {
            const float4* p = (const float4*)(Xb + (size_t)t_in * C_ * F_);
            float4 a = p[0], q = p[1];
            rw[slot][0] = pack_dup(a.x); rw[slot][1] = pack_dup(a.y);
            rw[slot][2] = pack_dup(a.z); rw[slot][3] = pack_dup(a.w);
            rw[slot][4] = pack_dup(q.x); rw[slot][5] = pack_dup(q.y);
            rw[slot][6] = pack_dup(q.z); rw[slot][7] = pack_dup(q.w);
        } else {
#pragma unroll
            for (int i = 0; i < 8; ++i) rw[slot][i] = 0ull;
        }
    }

#pragma unroll 1
    for (int kh0 = 0; kh0 < 32; kh0 += 4) {
#pragma unroll
        for (int u = 0; u < 4; ++u) {
            int kh = kh0 + u;
            const ull* kp = sK2 + kh * 32;
#pragma unroll
            for (int i = 0; i < 8; ++i) {
#pragma unroll
                for (int op = 0; op < 4; ++op) {
                    ull k2 = kp[i * 4 + op];
#pragma unroll
                    for (int tt = 0; tt < 4; ++tt)
                        acc[tt][op] = fma2(rw[(u + tt) & 3][i], k2, acc[tt][op]);
                }
            }
            if (kh < 31) {                        // refill slot u with row kh+4
                int t_in = t_first - PAD_ + kh + 4;
                if ((unsigned)t_in < (unsigned)T_) {
                    const float4* p = (const float4*)(Xb + (size_t)t_in * C_ * F_);
                    float4 a = p[0], q = p[1];
                    rw[u][0] = pack_dup(a.x); rw[u][1] = pack_dup(a.y);
                    rw[u][2] = pack_dup(a.z); rw[u][3] = pack_dup(a.w);
                    rw[u][4] = pack_dup(q.x); rw[u][5] = pack_dup(q.y);
                    rw[u][6] = pack_dup(q.z); rw[u][7] = pack_dup(q.w);
                } else {
#pragma unroll
                    for (int i = 0; i < 8; ++i) rw[u][i] = 0ull;
                }
            }
        }
    }

    // LayerNorm (eps 1e-6) + ReLU, write ann tile
#pragma unroll
    for (int tt = 0; tt < 4; ++tt) {
        float v[8];
#pragma unroll
        for (int op = 0; op < 4; ++op) unpack2(acc[tt][op], v[2 * op], v[2 * op + 1]);
        float mu = 0.f;
#pragma unroll
        for (int o = 0; o < 8; ++o) mu += v[o];
        mu *= 0.125f;
        float var = 0.f;
#pragma unroll
        for (int o = 0; o < 8; ++o) { float d = v[o] - mu; var += d * d; }
        var *= 0.125f;
        float inv = rsqrtf(var + 1e-6f);
        float* ap = sAnn + (g * 4 + tt) * 577 + c * 9;
#pragma unroll
        for (int o = 0; o < 8; ++o) {
            float a = (v[o] - mu) * inv * sLN[o] + sLN[8 + o];
            ap[o] = fmaxf(a, 0.f);
        }
    }
    __syncthreads();

    // projection: snn[b,t, s*8+f] = sum_c M[b,s,c] * ann[t,c,f]
    int tl      = tid >> 4;           // 0..7 local t
    int pairidx = tid & 15;
    int idx0    = pairidx * 2;        // even -> (idx0, idx0+1) share s
    int s       = idx0 >> 3;
    int f       = idx0 & 7;
    const float* mm = sM + s * 64;
    const float* ap = sAnn + tl * 577 + f;
    float a0 = 0.f, a1 = 0.f;
#pragma unroll 8
    for (int cc = 0; cc < 64; ++cc) {
        float mv = mm[cc];
        a0 += mv * ap[cc * 9];
        a1 += mv * ap[cc * 9 + 1];
    }
    float2* outp = (float2*)(g_snn + ((size_t)b * T_ + (t_blk + tl)) * 32 + idx0);
    *outp = make_float2(a0, a1);
}

// ---------------- K2: LIF scan + chunk means + spike counts ----------------
// grid 64 (b), block 32 (unit j). Strictly sequential in t per (b,j).
__global__ void k2_lif() {
    int b = blockIdx.x;
    int j = threadIdx.x;
    const float* p  = g_snn + (size_t)b * T_ * 32 + j;
    float*       fo = g_flat + b * 3072;
    float m1 = 0.f, m2 = 0.f, mo = 0.f;
    int cnt = 0;
    for (int k = 0; k < 48; ++k) {
        float sacc = 0.f, eacc = 0.f;
#pragma unroll 4
        for (int r = 0; r < 24; ++r) {
            float x = p[(k * 24 + r) * 32];
            m1 = m1 * 0.8f + x;
            float s1 = (m1 > 0.5f) ? 1.0f : 0.0f;
            m1 -= s1 * 0.5f;
            m2 = m2 * 0.9f + s1;
            float s2 = (m2 > 0.5f) ? 1.0f : 0.0f;
            m2 -= s2 * 0.5f;
            mo = mo * 0.95f + s2;
            cnt += (int)s1 + (int)s2;
            if (r < 12) sacc += mo; else eacc += mo;
        }
        fo[k * 64 + j]      = sacc / 12.0f;
        fo[k * 64 + 32 + j] = eacc / 12.0f;
    }
#pragma unroll
    for (int off = 16; off; off >>= 1) cnt += __shfl_down_sync(0xffffffffu, cnt, off);
    if (j == 0) atomicAdd(&g_spk, cnt);
}

// ---------------- K3: head MLP (GELU tanh) + logits + firing rate ----------
__global__ void k3_head(const float* __restrict__ W1, const float* __restrict__ b1,
                        const float* __restrict__ W2, const float* __restrict__ b2,
                        float* __restrict__ out, int out_size) {
    int b = blockIdx.x;
    int j = threadIdx.x;              // 32 threads
    const float* fb = g_flat + b * 3072;
    float acc = b1[j];
#pragma unroll 8
    for (int i = 0; i < 3072; ++i)
        acc += fb[i] * W1[i * 32 + j];
    // jax.nn.gelu approximate=True (tanh form)
    float x  = acc;
    float tn = tanhf(0.7978845608028654f * (x + 0.044715f * x * x * x));
    float y  = 0.5f * x * (1.0f + tn);
    __shared__ float sy[32];
    sy[j] = y;
    __syncwarp();
    if (j < 4) {
        float l = b2[j];
#pragma unroll
        for (int jj = 0; jj < 32; ++jj) l += sy[jj] * W2[jj * 4 + j];
        out[b * 4 + j] = l;
    }
    if (b == 0 && j == 0 && out_size > 256) {
        out[256] = (float)((double)g_spk / (2.0 * (double)B_ * (double)T_ * 32.0));
    }
}

// ---------------- launcher --------------------------------------------------
extern "C" void kernel_launch(void* const* d_in, const int* in_sizes, int n_in,
                              void* d_out, int out_size) {
    const float* Ln  = (const float*)d_in[0];   // L_norm  (B,C,C)
    const float* X   = (const float*)d_in[1];   // X_seq   (B,T,C,F)
    // d_in[2] = deterministic (unused)
    const float* Kg  = (const float*)d_in[3];   // conv_kernel (32,1,8,8)
    const float* lnS = (const float*)d_in[4];   // ln_scale (8)
    const float* lnB = (const float*)d_in[5];   // ln_bias  (8)
    const float* spw = (const float*)d_in[6];   // spatial_w (64,4)
    const float* W1  = (const float*)d_in[7];   // (3072,32)
    const float* b1  = (const float*)d_in[8];   // (32)
    const float* W2  = (const float*)d_in[9];   // (32,4)
    const float* b2  = (const float*)d_in[10];  // (4)
    float* out = (float*)d_out;

    // d_out is poisoned each replay; clear any elements we don't explicitly write
    cudaMemsetAsync(d_out, 0, (size_t)out_size * sizeof(float), 0);

    k0_prep<<<64, 256>>>(Ln, spw);
    dim3 g1(T_ / 8, B_);
    k1_conv<<<g1, 128>>>(X, Kg, lnS, lnB);
    k2_lif<<<64, 32>>>();
    k3_head<<<64, 32>>>(W1, b1, W2, b2, out, out_size);
}

// round 5
// speedup vs baseline: 1.4698x; 1.4698x over previous
#include <cuda_runtime.h>
#include <cstdint>

#define B_   64
#define T_   1152
#define C_   64
#define F_   8
#define KH_  32
#define PAD_ 15

typedef unsigned long long ull;

// ---------------- scratch (device globals; no allocation allowed) ----------
__device__ float g_M[B_ * 4 * C_];                      // folded spatial_w^T @ L_norm
__device__ float g_snn[(size_t)B_ * T_ * 32];           // snn_in (B,T,32)  ~9.4 MB
__device__ float g_flat[B_ * 3072];                     // chunk-mean features
__device__ int   g_spk;                                 // spike count (spk1+spk2)

// ---------------- f32x2 helpers (sm_100+) ----------------------------------
__device__ __forceinline__ ull pack_dup(float x) {
    unsigned int xi = __float_as_uint(x);
    ull r;
    asm("mov.b64 %0, {%1, %1};" : "=l"(r) : "r"(xi));
    return r;
}
__device__ __forceinline__ ull fma2(ull a, ull b, ull c) {
    ull d;
    asm("fma.rn.f32x2 %0, %1, %2, %3;" : "=l"(d) : "l"(a), "l"(b), "l"(c));
    return d;
}
__device__ __forceinline__ void unpack2(ull v, float& lo, float& hi) {
    unsigned int l, h;
    asm("mov.b64 {%0, %1}, %2;" : "=r"(l), "=r"(h) : "l"(v));
    lo = __uint_as_float(l);
    hi = __uint_as_float(h);
}

// ---------------- K0: fold spatial_w into L_norm, zero counters ------------
__global__ void k0_prep(const float* __restrict__ Ln, const float* __restrict__ spw) {
    int b   = blockIdx.x;
    int tid = threadIdx.x;          // 256 threads: (s,m)
    int s = tid >> 6, m = tid & 63;
    const float* L = Ln + b * 4096;
    float acc = 0.f;
#pragma unroll 8
    for (int c = 0; c < 64; ++c)
        acc += spw[c * 4 + s] * L[c * 64 + m];
    g_M[b * 256 + s * 64 + m] = acc;
    if (b == 0 && tid == 0) g_spk = 0;
}

// ---------------- K1: conv(32 taps) + LN + ReLU + M-projection -------------
// grid (T/8, B), block 128: tid = c (0..63) + 64*g (g=0,1); each thread does
// 4 consecutive timesteps via a rolling 4-row register window (f32x2-dup'd).
// Invariant: at the start of tap kh, slot (r & 3) holds relative row r for
// r in [kh, kh+3]; output tt at tap kh consumes row kh+tt. Rows run to
// kh_max + tt_max = 34, hence refills must continue while kh < 31.
__global__ void __launch_bounds__(128)
k1_conv(const float* __restrict__ X, const float* __restrict__ Kg,
        const float* __restrict__ lnS, const float* __restrict__ lnB) {
    __shared__ ull   sK2[1024];       // conv kernel as f32x2 pairs: [kh][i][op]
    __shared__ float sM[256];         // M[s][c] for this b
    __shared__ float sLN[16];         // scale[8], bias[8]
    __shared__ float sAnn[8 * 577];   // ann tile [t_loc][c*9 + o]

    int tid   = threadIdx.x;
    int b     = blockIdx.y;
    int t_blk = blockIdx.x * 8;

    const ull* Kg2 = (const ull*)Kg;
    for (int i = tid; i < 1024; i += 128) sK2[i] = Kg2[i];
    for (int i = tid; i < 256;  i += 128) sM[i]  = g_M[b * 256 + i];
    if (tid < 8) { sLN[tid] = lnS[tid]; sLN[8 + tid] = lnB[tid]; }
    __syncthreads();

    int c = tid & 63;
    int g = tid >> 6;
    int t_first = t_blk + g * 4;
    const float* Xb = X + ((size_t)b * T_ * C_ + c) * F_;

    ull rw[4][8];                     // rolling window of 4 input rows (dup'd)
    ull acc[4][4];                    // [tt][op]  (op packs channels 2op,2op+1)
#pragma unroll
    for (int tt = 0; tt < 4; ++tt)
#pragma unroll
        for (int op = 0; op < 4; ++op) acc[tt][op] = 0ull;

#pragma unroll
    for (int slot = 0; slot < 4; ++slot) {
        int t_in = t_first - PAD_ + slot;
        if ((unsigned)t_in < (unsigned)T_) {
            const float4* p = (const float4*)(Xb + (size_t)t_in * C_ * F_);
            float4 a = p[0], q = p[1];
            rw[slot][0] = pack_dup(a.x); rw[slot][1] = pack_dup(a.y);
            rw[slot][2] = pack_dup(a.z); rw[slot][3] = pack_dup(a.w);
            rw[slot][4] = pack_dup(q.x); rw[slot][5] = pack_dup(q.y);
            rw[slot][6] = pack_dup(q.z); rw[slot][7] = pack_dup(q.w);
        } else {
#pragma unroll
            for (int i = 0; i < 8; ++i) rw[slot][i] = 0ull;
        }
    }

#pragma unroll 1
    for (int kh0 = 0; kh0 < 32; kh0 += 4) {
#pragma unroll
        for (int u = 0; u < 4; ++u) {
            int kh = kh0 + u;
            const ull* kp = sK2 + kh * 32;
#pragma unroll
            for (int i = 0; i < 8; ++i) {
#pragma unroll
                for (int op = 0; op < 4; ++op) {
                    ull k2 = kp[i * 4 + op];
#pragma unroll
                    for (int tt = 0; tt < 4; ++tt)
                        acc[tt][op] = fma2(rw[(u + tt) & 3][i], k2, acc[tt][op]);
                }
            }
            if (kh < 31) {                        // refill slot u with row kh+4
                int t_in = t_first - PAD_ + kh + 4;
                if ((unsigned)t_in < (unsigned)T_) {
                    const float4* p = (const float4*)(Xb + (size_t)t_in * C_ * F_);
                    float4 a = p[0], q = p[1];
                    rw[u][0] = pack_dup(a.x); rw[u][1] = pack_dup(a.y);
                    rw[u][2] = pack_dup(a.z); rw[u][3] = pack_dup(a.w);
                    rw[u][4] = pack_dup(q.x); rw[u][5] = pack_dup(q.y);
                    rw[u][6] = pack_dup(q.z); rw[u][7] = pack_dup(q.w);
                } else {
#pragma unroll
                    for (int i = 0; i < 8; ++i) rw[u][i] = 0ull;
                }
            }
        }
    }

    // LayerNorm (eps 1e-6) + ReLU, write ann tile
#pragma unroll
    for (int tt = 0; tt < 4; ++tt) {
        float v[8];
#pragma unroll
        for (int op = 0; op < 4; ++op) unpack2(acc[tt][op], v[2 * op], v[2 * op + 1]);
        float mu = 0.f;
#pragma unroll
        for (int o = 0; o < 8; ++o) mu += v[o];
        mu *= 0.125f;
        float var = 0.f;
#pragma unroll
        for (int o = 0; o < 8; ++o) { float d = v[o] - mu; var += d * d; }
        var *= 0.125f;
        float inv = rsqrtf(var + 1e-6f);
        float* ap = sAnn + (g * 4 + tt) * 577 + c * 9;
#pragma unroll
        for (int o = 0; o < 8; ++o) {
            float a = (v[o] - mu) * inv * sLN[o] + sLN[8 + o];
            ap[o] = fmaxf(a, 0.f);
        }
    }
    __syncthreads();

    // projection: snn[b,t, s*8+f] = sum_c M[b,s,c] * ann[t,c,f]
    int tl      = tid >> 4;           // 0..7 local t
    int pairidx = tid & 15;
    int idx0    = pairidx * 2;        // even -> (idx0, idx0+1) share s
    int s       = idx0 >> 3;
    int f       = idx0 & 7;
    const float* mm = sM + s * 64;
    const float* ap = sAnn + tl * 577 + f;
    float a0 = 0.f, a1 = 0.f;
#pragma unroll 8
    for (int cc = 0; cc < 64; ++cc) {
        float mv = mm[cc];
        a0 += mv * ap[cc * 9];
        a1 += mv * ap[cc * 9 + 1];
    }
    float2* outp = (float2*)(g_snn + ((size_t)b * T_ + (t_blk + tl)) * 32 + idx0);
    *outp = make_float2(a0, a1);
}

// ---------------- K2: LIF scan + chunk means + spike counts ----------------
// grid 64 (b), block 32 (unit j). Strictly sequential in t per (b,j), but the
// LOADS are address-independent: double-buffer a full 24-step chunk in
// registers (MLP=24) while the LIF recurrence chews the previous chunk.
__global__ void k2_lif() {
    int b = blockIdx.x;
    int j = threadIdx.x;
    const float* p  = g_snn + (size_t)b * T_ * 32 + j;
    float*       fo = g_flat + b * 3072;
    float m1 = 0.f, m2 = 0.f, mo = 0.f;
    int cnt = 0;

    float cur[24], nxt[24];
#pragma unroll
    for (int r = 0; r < 24; ++r) cur[r] = p[r * 32];

    for (int k = 0; k < 48; ++k) {
        if (k < 47) {
            const float* pn = p + (size_t)(k + 1) * 24 * 32;
#pragma unroll
            for (int r = 0; r < 24; ++r) nxt[r] = pn[r * 32];
        }
        float sacc = 0.f, eacc = 0.f;
#pragma unroll
        for (int r = 0; r < 24; ++r) {
            float x = cur[r];
            m1 = m1 * 0.8f + x;
            float s1 = (m1 > 0.5f) ? 1.0f : 0.0f;
            m1 -= s1 * 0.5f;
            m2 = m2 * 0.9f + s1;
            float s2 = (m2 > 0.5f) ? 1.0f : 0.0f;
            m2 -= s2 * 0.5f;
            mo = mo * 0.95f + s2;
            cnt += (int)s1 + (int)s2;
            if (r < 12) sacc += mo; else eacc += mo;
        }
        fo[k * 64 + j]      = sacc / 12.0f;
        fo[k * 64 + 32 + j] = eacc / 12.0f;
#pragma unroll
        for (int r = 0; r < 24; ++r) cur[r] = nxt[r];
    }
#pragma unroll
    for (int off = 16; off; off >>= 1) cnt += __shfl_down_sync(0xffffffffu, cnt, off);
    if (j == 0) atomicAdd(&g_spk, cnt);
}

// ---------------- K3: head MLP (GELU tanh) + logits + firing rate ----------
// grid 64 (b), block 256: tid = j (0..31) + 32*slice (8 slices of 384 i's).
// Partial dot products in smem, warp 0 reduces + GELU + logits.
__global__ void __launch_bounds__(256)
k3_head(const float* __restrict__ W1, const float* __restrict__ b1,
        const float* __restrict__ W2, const float* __restrict__ b2,
        float* __restrict__ out, int out_size) {
    __shared__ float part[8][32];
    __shared__ float sy[32];

    int b   = blockIdx.x;
    int tid = threadIdx.x;
    int j   = tid & 31;
    int sl  = tid >> 5;               // 0..7

    const float* fb = g_flat + b * 3072 + sl * 384;
    const float* w  = W1 + (sl * 384) * 32 + j;
    float acc = 0.f;
#pragma unroll 8
    for (int i = 0; i < 384; ++i)
        acc += fb[i] * w[i * 32];
    part[sl][j] = acc;
    __syncthreads();

    if (tid < 32) {
        float a = b1[tid];
#pragma unroll
        for (int s = 0; s < 8; ++s) a += part[s][tid];
        // jax.nn.gelu approximate=True (tanh form)
        float x  = a;
        float tn = tanhf(0.7978845608028654f * (x + 0.044715f * x * x * x));
        sy[tid]  = 0.5f * x * (1.0f + tn);
        __syncwarp();
        if (tid < 4) {
            float l = b2[tid];
#pragma unroll
            for (int jj = 0; jj < 32; ++jj) l += sy[jj] * W2[jj * 4 + tid];
            out[b * 4 + tid] = l;
        }
        if (b == 0 && tid == 0 && out_size > 256) {
            out[256] = (float)((double)g_spk / (2.0 * (double)B_ * (double)T_ * 32.0));
        }
    }
}

// ---------------- launcher --------------------------------------------------
extern "C" void kernel_launch(void* const* d_in, const int* in_sizes, int n_in,
                              void* d_out, int out_size) {
    const float* Ln  = (const float*)d_in[0];   // L_norm  (B,C,C)
    const float* X   = (const float*)d_in[1];   // X_seq   (B,T,C,F)
    // d_in[2] = deterministic (unused)
    const float* Kg  = (const float*)d_in[3];   // conv_kernel (32,1,8,8)
    const float* lnS = (const float*)d_in[4];   // ln_scale (8)
    const float* lnB = (const float*)d_in[5];   // ln_bias  (8)
    const float* spw = (const float*)d_in[6];   // spatial_w (64,4)
    const float* W1  = (const float*)d_in[7];   // (3072,32)
    const float* b1  = (const float*)d_in[8];   // (32)
    const float* W2  = (const float*)d_in[9];   // (32,4)
    const float* b2  = (const float*)d_in[10];  // (4)
    float* out = (float*)d_out;

    // d_out is poisoned each replay; clear any elements we don't explicitly write
    cudaMemsetAsync(d_out, 0, (size_t)out_size * sizeof(float), 0);

    k0_prep<<<64, 256>>>(Ln, spw);
    dim3 g1(T_ / 8, B_);
    k1_conv<<<g1, 128>>>(X, Kg, lnS, lnB);
    k2_lif<<<64, 32>>>();
    k3_head<<<64, 256>>>(W1, b1, W2, b2, out, out_size);
}

// round 7
// speedup vs baseline: 1.5070x; 1.0253x over previous
#include <cuda_runtime.h>
#include <cstdint>

#define B_   64
#define T_   1152
#define C_   64
#define F_   8
#define KH_  32
#define PAD_ 15

typedef unsigned long long ull;

// ---------------- scratch (device globals; no allocation allowed) ----------
__device__ float g_M[B_ * 4 * C_];                      // folded spatial_w^T @ L_norm
__device__ float g_snn[(size_t)B_ * T_ * 32];           // snn_in (B,T,32)  ~9.4 MB
__device__ int   g_spk;                                 // spike count (spk1+spk2)

// ---------------- f32x2 helpers (sm_100+) ----------------------------------
__device__ __forceinline__ ull pack_dup(float x) {
    unsigned int xi = __float_as_uint(x);
    ull r;
    asm("mov.b64 %0, {%1, %1};" : "=l"(r) : "r"(xi));
    return r;
}
__device__ __forceinline__ ull fma2(ull a, ull b, ull c) {
    ull d;
    asm("fma.rn.f32x2 %0, %1, %2, %3;" : "=l"(d) : "l"(a), "l"(b), "l"(c));
    return d;
}
__device__ __forceinline__ void unpack2(ull v, float& lo, float& hi) {
    unsigned int l, h;
    asm("mov.b64 {%0, %1}, %2;" : "=r"(l), "=r"(h) : "l"(v));
    lo = __uint_as_float(l);
    hi = __uint_as_float(h);
}

// ---------------- K0: fold spatial_w into L_norm, zero counters ------------
__global__ void k0_prep(const float* __restrict__ Ln, const float* __restrict__ spw) {
    int b   = blockIdx.x;
    int tid = threadIdx.x;          // 256 threads: (s,m)
    int s = tid >> 6, m = tid & 63;
    const float* L = Ln + b * 4096;
    float acc = 0.f;
#pragma unroll 8
    for (int c = 0; c < 64; ++c)
        acc += spw[c * 4 + s] * L[c * 64 + m];
    g_M[b * 256 + s * 64 + m] = acc;
    if (b == 0 && tid == 0) g_spk = 0;
}

// ---------------- K1: conv(32 taps) + LN + ReLU + M-projection -------------
// grid (T/8, B), block 128: tid = c (0..63) + 64*g (g=0,1); each thread does
// 4 consecutive timesteps via a rolling 4-row register window (f32x2-dup'd).
// Invariant: at the start of tap kh, slot (r & 3) holds relative row r for
// r in [kh, kh+3]; output tt at tap kh consumes row kh+tt. Rows run to
// kh_max + tt_max = 34, hence refills must continue while kh < 31.
// Coefficients are read as 16B LDS.128 (two op-pairs per load).
__global__ void __launch_bounds__(128)
k1_conv(const float* __restrict__ X, const float* __restrict__ Kg,
        const float* __restrict__ lnS, const float* __restrict__ lnB) {
    __shared__ __align__(16) ull sK2[1024];  // conv kernel f32x2 pairs: [kh][i][op]
    __shared__ float sM[256];                // M[s][c] for this b
    __shared__ float sLN[16];                // scale[8], bias[8]
    __shared__ float sAnn[8 * 577];          // ann tile [t_loc][c*9 + o]

    int tid   = threadIdx.x;
    int b     = blockIdx.y;
    int t_blk = blockIdx.x * 8;

    const ull* Kg2 = (const ull*)Kg;
    for (int i = tid; i < 1024; i += 128) sK2[i] = Kg2[i];
    for (int i = tid; i < 256;  i += 128) sM[i]  = g_M[b * 256 + i];
    if (tid < 8) { sLN[tid] = lnS[tid]; sLN[8 + tid] = lnB[tid]; }
    __syncthreads();

    int c = tid & 63;
    int g = tid >> 6;
    int t_first = t_blk + g * 4;
    const float* Xb = X + ((size_t)b * T_ * C_ + c) * F_;

    ull rw[4][8];                     // rolling window of 4 input rows (dup'd)
    ull acc[4][4];                    // [tt][op]  (op packs channels 2op,2op+1)
#pragma unroll
    for (int tt = 0; tt < 4; ++tt)
#pragma unroll
        for (int op = 0; op < 4; ++op) acc[tt][op] = 0ull;

#pragma unroll
    for (int slot = 0; slot < 4; ++slot) {
        int t_in = t_first - PAD_ + slot;
        if ((unsigned)t_in < (unsigned)T_) {
            const float4* p = (const float4*)(Xb + (size_t)t_in * C_ * F_);
            float4 a = p[0], q = p[1];
            rw[slot][0] = pack_dup(a.x); rw[slot][1] = pack_dup(a.y);
            rw[slot][2] = pack_dup(a.z); rw[slot][3] = pack_dup(a.w);
            rw[slot][4] = pack_dup(q.x); rw[slot][5] = pack_dup(q.y);
            rw[slot][6] = pack_dup(q.z); rw[slot][7] = pack_dup(q.w);
        } else {
#pragma unroll
            for (int i = 0; i < 8; ++i) rw[slot][i] = 0ull;
        }
    }

#pragma unroll 1
    for (int kh0 = 0; kh0 < 32; kh0 += 4) {
#pragma unroll
        for (int u = 0; u < 4; ++u) {
            int kh = kh0 + u;
            const ulonglong2* kp2 = (const ulonglong2*)(sK2 + kh * 32);
#pragma unroll
            for (int i = 0; i < 8; ++i) {
#pragma unroll
                for (int opp = 0; opp < 2; ++opp) {
                    ulonglong2 kk = kp2[i * 2 + opp];
#pragma unroll
                    for (int tt = 0; tt < 4; ++tt) {
                        ull x = rw[(u + tt) & 3][i];
                        acc[tt][2 * opp]     = fma2(x, kk.x, acc[tt][2 * opp]);
                        acc[tt][2 * opp + 1] = fma2(x, kk.y, acc[tt][2 * opp + 1]);
                    }
                }
            }
            if (kh < 31) {                        // refill slot u with row kh+4
                int t_in = t_first - PAD_ + kh + 4;
                if ((unsigned)t_in < (unsigned)T_) {
                    const float4* p = (const float4*)(Xb + (size_t)t_in * C_ * F_);
                    float4 a = p[0], q = p[1];
                    rw[u][0] = pack_dup(a.x); rw[u][1] = pack_dup(a.y);
                    rw[u][2] = pack_dup(a.z); rw[u][3] = pack_dup(a.w);
                    rw[u][4] = pack_dup(q.x); rw[u][5] = pack_dup(q.y);
                    rw[u][6] = pack_dup(q.z); rw[u][7] = pack_dup(q.w);
                } else {
#pragma unroll
                    for (int i = 0; i < 8; ++i) rw[u][i] = 0ull;
                }
            }
        }
    }

    // LayerNorm (eps 1e-6) + ReLU, write ann tile
#pragma unroll
    for (int tt = 0; tt < 4; ++tt) {
        float v[8];
#pragma unroll
        for (int op = 0; op < 4; ++op) unpack2(acc[tt][op], v[2 * op], v[2 * op + 1]);
        float mu = 0.f;
#pragma unroll
        for (int o = 0; o < 8; ++o) mu += v[o];
        mu *= 0.125f;
        float var = 0.f;
#pragma unroll
        for (int o = 0; o < 8; ++o) { float d = v[o] - mu; var += d * d; }
        var *= 0.125f;
        float inv = rsqrtf(var + 1e-6f);
        float* ap = sAnn + (g * 4 + tt) * 577 + c * 9;
#pragma unroll
        for (int o = 0; o < 8; ++o) {
            float a = (v[o] - mu) * inv * sLN[o] + sLN[8 + o];
            ap[o] = fmaxf(a, 0.f);
        }
    }
    __syncthreads();

    // projection: snn[b,t, s*8+f] = sum_c M[b,s,c] * ann[t,c,f]
    int tl      = tid >> 4;           // 0..7 local t
    int pairidx = tid & 15;
    int idx0    = pairidx * 2;        // even -> (idx0, idx0+1) share s
    int s       = idx0 >> 3;
    int f       = idx0 & 7;
    const float* mm = sM + s * 64;
    const float* ap = sAnn + tl * 577 + f;
    float a0 = 0.f, a1 = 0.f;
#pragma unroll 8
    for (int cc = 0; cc < 64; ++cc) {
        float mv = mm[cc];
        a0 += mv * ap[cc * 9];
        a1 += mv * ap[cc * 9 + 1];
    }
    float2* outp = (float2*)(g_snn + ((size_t)b * T_ + (t_blk + tl)) * 32 + idx0);
    *outp = make_float2(a0, a1);
}

// ---------------- K2: LIF scan + chunk means + head MLP (fused) ------------
// grid 64 (b), block 256. Warp 0 (32 lanes = units) runs the strictly
// sequential LIF recurrence with register double-buffered chunk loads,
// writing chunk means into smem. Then all 8 warps do the 3072x32 GEMV from
// smem, warp 0 finishes GELU + logits.
__global__ void __launch_bounds__(256)
k2_lif_head(const float* __restrict__ W1, const float* __restrict__ b1,
            const float* __restrict__ W2, const float* __restrict__ b2,
            float* __restrict__ out) {
    __shared__ float sflat[3072];
    __shared__ float part[8][32];
    __shared__ float sy[32];

    int b   = blockIdx.x;
    int tid = threadIdx.x;

    if (tid < 32) {
        int j = tid;
        const float* p = g_snn + (size_t)b * T_ * 32 + j;
        float m1 = 0.f, m2 = 0.f, mo = 0.f;
        int cnt = 0;

        float cur[24], nxt[24];
#pragma unroll
        for (int r = 0; r < 24; ++r) cur[r] = p[r * 32];

        for (int k = 0; k < 48; ++k) {
            if (k < 47) {
                const float* pn = p + (size_t)(k + 1) * 24 * 32;
#pragma unroll
                for (int r = 0; r < 24; ++r) nxt[r] = pn[r * 32];
            }
            float sacc = 0.f, eacc = 0.f;
#pragma unroll
            for (int r = 0; r < 24; ++r) {
                float x = cur[r];
                m1 = m1 * 0.8f + x;
                float s1 = (m1 > 0.5f) ? 1.0f : 0.0f;
                m1 -= s1 * 0.5f;
                m2 = m2 * 0.9f + s1;
                float s2 = (m2 > 0.5f) ? 1.0f : 0.0f;
                m2 -= s2 * 0.5f;
                mo = mo * 0.95f + s2;
                cnt += (int)s1 + (int)s2;
                if (r < 12) sacc += mo; else eacc += mo;
            }
            sflat[k * 64 + j]      = sacc / 12.0f;
            sflat[k * 64 + 32 + j] = eacc / 12.0f;
#pragma unroll
            for (int r = 0; r < 24; ++r) cur[r] = nxt[r];
        }
#pragma unroll
        for (int off = 16; off; off >>= 1) cnt += __shfl_down_sync(0xffffffffu, cnt, off);
        if (j == 0) atomicAdd(&g_spk, cnt);
    }
    __syncthreads();

    // GEMV: y = flat @ W1 (+b1); 8 i-slices of 384, partials in smem
    {
        int j  = tid & 31;
        int sl = tid >> 5;            // 0..7
        const float* fb = sflat + sl * 384;
        const float* w  = W1 + (sl * 384) * 32 + j;
        float acc = 0.f;
#pragma unroll 8
        for (int i = 0; i < 384; ++i)
            acc += fb[i] * w[i * 32];
        part[sl][j] = acc;
    }
    __syncthreads();

    if (tid < 32) {
        float a = b1[tid];
#pragma unroll
        for (int s = 0; s < 8; ++s) a += part[s][tid];
        // jax.nn.gelu approximate=True (tanh form)
        float x  = a;
        float tn = tanhf(0.7978845608028654f * (x + 0.044715f * x * x * x));
        sy[tid]  = 0.5f * x * (1.0f + tn);
        __syncwarp();
        if (tid < 4) {
            float l = b2[tid];
#pragma unroll
            for (int jj = 0; jj < 32; ++jj) l += sy[jj] * W2[jj * 4 + tid];
            out[b * 4 + tid] = l;
        }
    }
}

// ---------------- K4: firing rate (after grid-wide spike atomic) -----------
__global__ void k4_rate(float* __restrict__ out, int out_size) {
    if (out_size > 256)
        out[256] = (float)((double)g_spk / (2.0 * (double)B_ * (double)T_ * 32.0));
}

// ---------------- launcher --------------------------------------------------
extern "C" void kernel_launch(void* const* d_in, const int* in_sizes, int n_in,
                              void* d_out, int out_size) {
    const float* Ln  = (const float*)d_in[0];   // L_norm  (B,C,C)
    const float* X   = (const float*)d_in[1];   // X_seq   (B,T,C,F)
    // d_in[2] = deterministic (unused)
    const float* Kg  = (const float*)d_in[3];   // conv_kernel (32,1,8,8)
    const float* lnS = (const float*)d_in[4];   // ln_scale (8)
    const float* lnB = (const float*)d_in[5];   // ln_bias  (8)
    const float* spw = (const float*)d_in[6];   // spatial_w (64,4)
    const float* W1  = (const float*)d_in[7];   // (3072,32)
    const float* b1  = (const float*)d_in[8];   // (32)
    const float* W2  = (const float*)d_in[9];   // (32,4)
    const float* b2  = (const float*)d_in[10];  // (4)
    float* out = (float*)d_out;

    // d_out is poisoned each replay; clear any elements we don't explicitly write
    cudaMemsetAsync(d_out, 0, (size_t)out_size * sizeof(float), 0);

    k0_prep<<<64, 256>>>(Ln, spw);
    dim3 g1(T_ / 8, B_);
    k1_conv<<<g1, 128>>>(X, Kg, lnS, lnB);
    k2_lif_head<<<64, 256>>>(W1, b1, W2, b2, out);
    k4_rate<<<1, 1>>>(out, out_size);
}